// round 9
// baseline (speedup 1.0000x reference)
#include <cuda_runtime.h>
#include <math.h>

// ---------------------------------------------------------------------------
// DilatedSparseRnnStack — R9: 2 gate-columns per thread (j, j+128) so each
// xh LDS feeds 2x the FFMA work -> GEMM LDS stream halves and FFMA2 becomes
// the single ceiling. 512 threads = 4 k-quarters x 128 j-threads. 4-way
// reduction via 128KB SMEM buffer; biases in SMEM; state layout from R8.
// ---------------------------------------------------------------------------

namespace {
constexpr int T_STEPS = 256;
constexpr int BATCH   = 1024;
constexpr int IN_F    = 64;
constexpr int SSZ     = 256;
constexpr int HSZ     = 128;
constexpr int OSZ     = 128;
constexpr int OUT_F   = 8;
constexpr int RPC     = 8;
constexpr int NCTA    = BATCH / RPC;   // 128
constexpr int NTHR    = 512;
constexpr int KTOT    = 320 + 384 + 448 + 384;  // 1536

// dynamic SMEM layout (bytes)
constexpr int SM_XH    = 0;        // 448*8*4 = 14336
constexpr int SM_RED   = 14336;    // 32*4*128*8 = 131072
constexpr int SM_OUT   = 145408;   // 4096
constexpr int SM_WOUT  = 149504;   // 4096
constexpr int SM_BIAS  = 153600;   // 4*256*16 = 16384
constexpr int SM_TOTAL = 169984;
}

// Transposed, gate-interleaved weights: per layer [K][1024], fast index 4*j+g.
__device__ float g_WT[(size_t)KTOT * 1024];

// Circular dilation buffers, CTA-local layout:
//   C: [slot 22][group 128][j 256][r 8]
//   H: [slot 22][group 128][jh 128][r 8]
__device__ float4 g_bufC4[22u * 128 * 256 * 2];
__device__ float4 g_bufH4[22u * 128 * 128 * 2];

__device__ __forceinline__ float sigf(float v) {
    return 1.0f / (1.0f + __expf(-v));
}
__device__ __forceinline__ void ffma2(unsigned long long& d,
                                      unsigned long long a,
                                      unsigned long long b) {
    asm("fma.rn.f32x2 %0, %1, %2, %0;" : "+l"(d) : "l"(a), "l"(b));
}
__device__ __forceinline__ void fadd2(unsigned long long& d,
                                      unsigned long long a) {
    asm("add.rn.f32x2 %0, %0, %1;" : "+l"(d) : "l"(a));
}
__device__ __forceinline__ unsigned long long dup2(float w) {
    unsigned long long r;
    asm("mov.b64 %0, {%1, %1};" : "=l"(r) : "f"(w));
    return r;
}
__device__ __forceinline__ float2 u2f2(unsigned long long v) {
    float2 f;
    asm("mov.b64 {%0, %1}, %2;" : "=f"(f.x), "=f"(f.y) : "l"(v));
    return f;
}

// ---------------------------------------------------------------------------
// Prep: transpose + gate-interleave weights (read-coalesced over W).
// ---------------------------------------------------------------------------
__global__ void prep_kernel(const float* __restrict__ W0,
                            const float* __restrict__ W1,
                            const float* __restrict__ W2,
                            const float* __restrict__ W3)
{
    const int li = blockIdx.y;
    const float* W;
    int K, off;
    if (li == 0)      { W = W0; K = 320; off = 0; }
    else if (li == 1) { W = W1; K = 384; off = 320 * 1024; }
    else if (li == 2) { W = W2; K = 448; off = 704 * 1024; }
    else              { W = W3; K = 384; off = 1152 * 1024; }

    int idx = blockIdx.x * 256 + threadIdx.x;
    if (idx < 1024 * K) {
        int row = idx / K;           // g*256 + j
        int k   = idx - row * K;
        int g = row >> 8, j = row & 255;
        g_WT[(size_t)off + (size_t)k * 1024 + 4 * j + g] = W[idx];
    }
}

// ---------------------------------------------------------------------------
// One layer step. 512 threads: q = tid>>7 (k-quarter, owns row-pair q),
// j0 = tid&127 (columns j0 and j0+128).
// ---------------------------------------------------------------------------
template <int K, int DIL, int LOFF, int LI, int WTOFF>
__device__ __forceinline__ void do_layer(
    int t, int tid, int group,
    const float* __restrict__ xt,
    char* __restrict__ smem)
{
    const int prevSlot = LOFF + (t - 1 + DIL) % DIL;
    const int curSlot  = LOFF + (t % DIL);
    const int q  = tid >> 7;
    const int j0 = tid & 127;

    float* s_xhf = reinterpret_cast<float*>(smem + SM_XH);
    unsigned long long* s_red =
        reinterpret_cast<unsigned long long*>(smem + SM_RED);
    float* s_out = reinterpret_cast<float*>(smem + SM_OUT);

    __syncthreads();  // sync A: prev layer fully consumed

    // ---- C-state prefetch: float2 of owned rows {2q, 2q+1}, both cols ----
    float2* Cb2 = reinterpret_cast<float2*>(g_bufC4);
    const size_t cbase = (size_t)(curSlot  * 128 + group) * 256;
    const size_t pbase = (size_t)(prevSlot * 128 + group) * 256;
    float2 pC[2] = {make_float2(0.f, 0.f), make_float2(0.f, 0.f)};
    float2 dC[2] = {make_float2(0.f, 0.f), make_float2(0.f, 0.f)};
    if (t > 0) {
        pC[0] = Cb2[(pbase + j0) * 4 + q];
        pC[1] = Cb2[(pbase + j0 + 128) * 4 + q];
    }
    if (t >= DIL) {
        dC[0] = Cb2[(cbase + j0) * 4 + q];
        dC[1] = Cb2[(cbase + j0 + 128) * 4 + q];
    }

    // ---- build xh in SMEM: s_xhf[k*8 + r] ----
    if (LI > 0) {
        // out section at k-offset 0: s_out[j*8+r] -> identity index mapping
        s_xhf[tid]       = s_out[tid];
        s_xhf[tid + 512] = s_out[tid + 512];
    }
    if (LI == 0 || LI == 2) {
        constexpr int XOFF = (LI == 0) ? 0 : OSZ;
        if (tid < 128) {
            int r = tid & 7, k4 = tid >> 3;          // k4 in 0..15
            const float4 v = reinterpret_cast<const float4*>(xt)[r * (IN_F / 4) + k4];
            int b = (XOFF + 4 * k4) * 8 + r;
            s_xhf[b]      = v.x;
            s_xhf[b + 8]  = v.y;
            s_xhf[b + 16] = v.z;
            s_xhf[b + 24] = v.w;
        }
    }
    {
        // prevH (sel 0) / dH (sel 1): coalesced LDG.128 -> STS.128
        constexpr int HOFF = (LI == 0) ? IN_F : (LI == 2) ? (OSZ + IN_F) : OSZ;
        const int sel = tid >> 8;                    // 0 or 1
        const int jj  = tid & 255;
        const int slotH = (sel == 0) ? prevSlot
                                     : ((t >= DIL) ? curSlot : prevSlot);
        float4 v = make_float4(0.f, 0.f, 0.f, 0.f);
        if (t > 0) {
            v = g_bufH4[((size_t)(slotH * 128 + group) * 128) * 2 + jj];
        }
        const int jh = jj >> 1, r0 = (jj & 1) * 4;
        const int dst = (HOFF + sel * HSZ + jh) * 8 + r0;
        *reinterpret_cast<float4*>(&s_xhf[dst]) = v;
    }

    __syncthreads();  // sync B: xh complete

    // ---- GEMM over quarter q, 2 columns, row-pair packing ----
    // aG[g][c][p]: ull = (row 2p, row 2p+1) for gate g, column c.
    unsigned long long a0[2][4], a1[2][4], a2[2][4], a3[2][4];
#pragma unroll
    for (int c = 0; c < 2; ++c)
#pragma unroll
        for (int p = 0; p < 4; ++p) {
            a0[c][p] = a1[c][p] = a2[c][p] = a3[c][p] = 0ull;
        }

    {
        const char* wp = reinterpret_cast<const char*>(g_WT + WTOFF)
                       + (size_t)j0 * 16 + (size_t)q * (K / 4) * 4096;
        const char* xp = smem + SM_XH + q * (K / 4) * 32;
        for (int kb = 0; kb < K / 4; kb += 4) {
#pragma unroll
            for (int u = 0; u < 4; ++u) {
                float4 wA = *reinterpret_cast<const float4*>(wp + u * 4096);
                float4 wB = *reinterpret_cast<const float4*>(wp + u * 4096 + 2048);
                ulonglong2 xA = *reinterpret_cast<const ulonglong2*>(xp + u * 32);
                ulonglong2 xB = *reinterpret_cast<const ulonglong2*>(xp + u * 32 + 16);
                unsigned long long wA0 = dup2(wA.x), wA1 = dup2(wA.y);
                unsigned long long wA2 = dup2(wA.z), wA3 = dup2(wA.w);
                unsigned long long wB0 = dup2(wB.x), wB1 = dup2(wB.y);
                unsigned long long wB2 = dup2(wB.z), wB3 = dup2(wB.w);
                ffma2(a0[0][0], wA0, xA.x); ffma2(a0[0][1], wA0, xA.y);
                ffma2(a0[0][2], wA0, xB.x); ffma2(a0[0][3], wA0, xB.y);
                ffma2(a1[0][0], wA1, xA.x); ffma2(a1[0][1], wA1, xA.y);
                ffma2(a1[0][2], wA1, xB.x); ffma2(a1[0][3], wA1, xB.y);
                ffma2(a2[0][0], wA2, xA.x); ffma2(a2[0][1], wA2, xA.y);
                ffma2(a2[0][2], wA2, xB.x); ffma2(a2[0][3], wA2, xB.y);
                ffma2(a3[0][0], wA3, xA.x); ffma2(a3[0][1], wA3, xA.y);
                ffma2(a3[0][2], wA3, xB.x); ffma2(a3[0][3], wA3, xB.y);
                ffma2(a0[1][0], wB0, xA.x); ffma2(a0[1][1], wB0, xA.y);
                ffma2(a0[1][2], wB0, xB.x); ffma2(a0[1][3], wB0, xB.y);
                ffma2(a1[1][0], wB1, xA.x); ffma2(a1[1][1], wB1, xA.y);
                ffma2(a1[1][2], wB1, xB.x); ffma2(a1[1][3], wB1, xB.y);
                ffma2(a2[1][0], wB2, xA.x); ffma2(a2[1][1], wB2, xA.y);
                ffma2(a2[1][2], wB2, xB.x); ffma2(a2[1][3], wB2, xB.y);
                ffma2(a3[1][0], wB3, xA.x); ffma2(a3[1][1], wB3, xA.y);
                ffma2(a3[1][2], wB3, xB.x); ffma2(a3[1][3], wB3, xB.y);
            }
            wp += 4 * 4096;
            xp += 4 * 32;
        }
    }

    // ---- write partials for NON-owned row-pairs ----
    // slot = (((c*4 + g)*4 + p)*4 + writer)*128 + j0
#pragma unroll
    for (int c = 0; c < 2; ++c) {
#pragma unroll
        for (int p = 0; p < 4; ++p) {
            if (p != q) {
                s_red[(((c * 4 + 0) * 4 + p) * 4 + q) * 128 + j0] = a0[c][p];
                s_red[(((c * 4 + 1) * 4 + p) * 4 + q) * 128 + j0] = a1[c][p];
                s_red[(((c * 4 + 2) * 4 + p) * 4 + q) * 128 + j0] = a2[c][p];
                s_red[(((c * 4 + 3) * 4 + p) * 4 + q) * 128 + j0] = a3[c][p];
            }
        }
    }

    __syncthreads();  // sync D: partials visible

#pragma unroll
    for (int c = 0; c < 2; ++c) {
#pragma unroll
        for (int w = 0; w < 4; ++w) {
            if (w != q) {
                fadd2(a0[c][q], s_red[(((c * 4 + 0) * 4 + q) * 4 + w) * 128 + j0]);
                fadd2(a1[c][q], s_red[(((c * 4 + 1) * 4 + q) * 4 + w) * 128 + j0]);
                fadd2(a2[c][q], s_red[(((c * 4 + 2) * 4 + q) * 4 + w) * 128 + j0]);
                fadd2(a3[c][q], s_red[(((c * 4 + 3) * 4 + q) * 4 + w) * 128 + j0]);
            }
        }
    }

    // ---- epilogue: owned rows {2q, 2q+1}, both columns ----
    const float4* s_bias = reinterpret_cast<const float4*>(smem + SM_BIAS);
    float2* Hb2 = reinterpret_cast<float2*>(g_bufH4);
    float2* s_out2 = reinterpret_cast<float2*>(s_out);

#pragma unroll
    for (int c = 0; c < 2; ++c) {
        const int jc = j0 + c * 128;
        const float4 bias = s_bias[LI * 256 + jc];
        float2 G0 = u2f2(a0[c][q]);
        float2 G1 = u2f2(a1[c][q]);
        float2 G2 = u2f2(a2[c][q]);
        float2 G3 = u2f2(a3[c][q]);
        float nc[2], wh[2];
#pragma unroll
        for (int s = 0; s < 2; ++s) {
            float forget = sigf((s ? G0.y : G0.x) + bias.x + 1.0f);
            float cand   = tanhf((s ? G1.y : G1.x) + bias.y);
            float alpha  = sigf((s ? G2.y : G2.x) + bias.z);
            float og     = sigf((s ? G3.y : G3.x) + bias.w);
            float pc = s ? pC[c].y : pC[c].x;
            float dc = s ? dC[c].y : dC[c].x;
            float newC;
            if (t == 0) {
                newC = cand;
            } else {
                float wC = pc;
                if (t >= DIL) {
                    wC = alpha * pc + (1.0f - alpha) * dc;
                }
                newC = forget * wC + (1.0f - forget) * cand;
            }
            nc[s] = newC;
            wh[s] = og * newC;
        }
        Cb2[(cbase + jc) * 4 + q] = make_float2(nc[0], nc[1]);
        if (c == 0) {
            s_out2[j0 * 4 + q] = make_float2(wh[0], wh[1]);
        } else {
            Hb2[((size_t)(curSlot * 128 + group) * 128 + j0) * 4 + q] =
                make_float2(wh[0], wh[1]);
        }
    }
}

__global__ __launch_bounds__(NTHR, 1) void rnn_stack_kernel(
    const float* __restrict__ x,
    const float* __restrict__ b0, const float* __restrict__ b1,
    const float* __restrict__ b2, const float* __restrict__ b3,
    const float* __restrict__ Wout, const float* __restrict__ bout,
    float* __restrict__ out)
{
    extern __shared__ char smem[];
    float* s_out  = reinterpret_cast<float*>(smem + SM_OUT);
    float* s_wout = reinterpret_cast<float*>(smem + SM_WOUT);

    const int tid   = threadIdx.x;
    const int group = blockIdx.x;
    const int row0  = group * RPC;

    if (tid < 256) {
        reinterpret_cast<float4*>(s_wout)[tid] =
            reinterpret_cast<const float4*>(Wout)[tid];
    }
    // bias table: 4 layers x 256 j
#pragma unroll
    for (int e = tid; e < 1024; e += NTHR) {
        int li = e >> 8, jj = e & 255;
        const float* bp = (li == 0) ? b0 : (li == 1) ? b1 : (li == 2) ? b2 : b3;
        reinterpret_cast<float4*>(smem + SM_BIAS)[e] =
            make_float4(bp[jj], bp[256 + jj], bp[512 + jj], bp[768 + jj]);
    }

    // projection mapping: seg = tid&7 (k-segment), o = (tid>>3)&7, r = tid>>6
    const int p_seg = tid & 7;
    const int p_o   = (tid >> 3) & 7;
    const int p_r   = tid >> 6;
    const float bo  = bout[p_o];

    for (int t = 0; t < T_STEPS; ++t) {
        const float* xt = x + ((size_t)t * BATCH + row0) * IN_F;

        do_layer<320,  1,  0, 0, 0>          (t, tid, group, xt, smem);
        do_layer<384,  3,  1, 1, 320 * 1024> (t, tid, group, xt, smem);
        do_layer<448,  6,  4, 2, 704 * 1024> (t, tid, group, xt, smem);
        do_layer<384, 12, 10, 3, 1152 * 1024>(t, tid, group, xt, smem);

        __syncthreads();  // layer-3 s_out ready

        // ---- output projection: all 512 threads, shfl octet reduction ----
        {
            float acc = 0.f;
#pragma unroll
            for (int qq = 0; qq < 16; ++qq) {
                int qv = qq * 8 + p_seg;
                acc = fmaf(s_out[qv * 8 + p_r], s_wout[p_o * OSZ + qv], acc);
            }
            acc += __shfl_down_sync(0xffffffffu, acc, 4, 8);
            acc += __shfl_down_sync(0xffffffffu, acc, 2, 8);
            acc += __shfl_down_sync(0xffffffffu, acc, 1, 8);
            if (p_seg == 0) {
                out[((size_t)t * BATCH + row0 + p_r) * OUT_F + p_o] = acc + bo;
            }
        }
        // next iteration's sync A protects s_out / smem reuse
    }
}

extern "C" void kernel_launch(void* const* d_in, const int* in_sizes, int n_in,
                              void* d_out, int out_size)
{
    (void)in_sizes; (void)n_in; (void)out_size;

    cudaFuncSetAttribute(rnn_stack_kernel,
                         cudaFuncAttributeMaxDynamicSharedMemorySize, SM_TOTAL);

    dim3 pgrid((1024 * 448 + 255) / 256, 4);
    prep_kernel<<<pgrid, 256>>>(
        (const float*)d_in[1], (const float*)d_in[3],
        (const float*)d_in[5], (const float*)d_in[7]);

    rnn_stack_kernel<<<NCTA, NTHR, SM_TOTAL>>>(
        (const float*)d_in[0],
        (const float*)d_in[2], (const float*)d_in[4],
        (const float*)d_in[6], (const float*)d_in[8],
        (const float*)d_in[9], (const float*)d_in[10],
        (float*)d_out);
}